// round 1
// baseline (speedup 1.0000x reference)
#include <cuda_runtime.h>
#include <math.h>

// Problem constants
#define B_  8
#define A_  6
#define QS_ 32
#define KS_ 1024
#define C_  256
#define H_  64
#define W_DIM 64
#define NSPAT (C_ * H_ * W_DIM)      // 1048576 per (b, agent)
#define N4 (NSPAT / 4)               // 262144 float4 per (b, agent)
#define OUT_MAIN ((size_t)B_ * A_ * NSPAT)  // 50331648

// scratch for the 8 x 6 x 6 softmaxed attention (allocation-free: device global)
__device__ float g_attn[B_ * A_ * A_];

// --------------------------------------------------------------------------
// Kernel 1: query projection + attention scores + softmax over key dim.
// One block per batch. Writes attn_sm to g_attn and (optionally) out tail.
// --------------------------------------------------------------------------
__global__ void attn_small_kernel(const float* __restrict__ qu,   // [B, A, QS]
                                  const float* __restrict__ kmat, // [B, A, KS]
                                  const float* __restrict__ Wm,   // [KS, QS]
                                  const float* __restrict__ bias, // [KS]
                                  float* __restrict__ out_tail,   // [B, A, A] or null
                                  int write_tail) {
    const int b = blockIdx.x;
    const int tid = threadIdx.x;

    __shared__ float s_qu[A_ * QS_];      // 192
    __shared__ float s_query[A_ * KS_];   // 6144 floats = 24 KB
    __shared__ float s_attn[A_ * A_];     // 36

    for (int i = tid; i < A_ * QS_; i += blockDim.x)
        s_qu[i] = qu[b * A_ * QS_ + i];
    __syncthreads();

    // query[qa][d] = sum_j qu[qa][j] * W[d][j] + bias[d]
    for (int i = tid; i < A_ * KS_; i += blockDim.x) {
        const int qa = i >> 10;          // / 1024
        const int d  = i & (KS_ - 1);    // % 1024
        float s = bias[d];
        const float* wrow = Wm + d * QS_;
        const float* qrow = s_qu + qa * QS_;
        #pragma unroll
        for (int j = 0; j < QS_; j++) s += qrow[j] * wrow[j];
        s_query[qa * KS_ + d] = s;
    }
    __syncthreads();

    // attn[kk][qq] = dot(k[b,kk,:], query[qq,:]) over d=1024  (36 pairs, 8 warps)
    const int warp = tid >> 5, lane = tid & 31;
    for (int p = warp; p < A_ * A_; p += (blockDim.x >> 5)) {
        const int kk = p / A_, qq = p % A_;
        const float* krow = kmat + ((size_t)b * A_ + kk) * KS_;
        const float* qrow = s_query + qq * KS_;
        float s = 0.f;
        for (int d = lane; d < KS_; d += 32) s += krow[d] * qrow[d];
        #pragma unroll
        for (int off = 16; off; off >>= 1)
            s += __shfl_down_sync(0xffffffffu, s, off);
        if (lane == 0) s_attn[kk * A_ + qq] = s;
    }
    __syncthreads();

    // softmax over kk (axis=1 of [B, K, Q]) for each qq
    if (tid < A_) {
        const int qq = tid;
        float m = -INFINITY;
        #pragma unroll
        for (int kk = 0; kk < A_; kk++) m = fmaxf(m, s_attn[kk * A_ + qq]);
        float e[A_], sum = 0.f;
        #pragma unroll
        for (int kk = 0; kk < A_; kk++) {
            e[kk] = expf(s_attn[kk * A_ + qq] - m);
            sum += e[kk];
        }
        const float inv = 1.f / sum;
        #pragma unroll
        for (int kk = 0; kk < A_; kk++) {
            const float a = e[kk] * inv;
            g_attn[b * 36 + kk * A_ + qq] = a;
            if (write_tail) out_tail[b * 36 + kk * A_ + qq] = a;
        }
    }
}

// --------------------------------------------------------------------------
// Kernel 2: out[b,q,x] = sum_k attn_sm[b,k,q] * v[b,k,x]  (x = c*h*w flat)
// HBM-bound streaming: 6 float4 loads -> 6 float4 stores per thread.
// --------------------------------------------------------------------------
__global__ void __launch_bounds__(256)
combine_kernel(const float4* __restrict__ v, float4* __restrict__ out) {
    const int b = blockIdx.y;
    const int x = blockIdx.x * blockDim.x + threadIdx.x;   // 0 .. N4-1

    __shared__ float s_a[A_ * A_];
    if (threadIdx.x < A_ * A_) s_a[threadIdx.x] = g_attn[b * 36 + threadIdx.x];
    __syncthreads();

    float4 vv[A_];
    #pragma unroll
    for (int kk = 0; kk < A_; kk++)
        vv[kk] = v[((size_t)(b * A_ + kk)) * N4 + x];

    #pragma unroll
    for (int qq = 0; qq < A_; qq++) {
        float4 o = make_float4(0.f, 0.f, 0.f, 0.f);
        #pragma unroll
        for (int kk = 0; kk < A_; kk++) {
            const float a = s_a[kk * A_ + qq];
            o.x = fmaf(a, vv[kk].x, o.x);
            o.y = fmaf(a, vv[kk].y, o.y);
            o.z = fmaf(a, vv[kk].z, o.z);
            o.w = fmaf(a, vv[kk].w, o.w);
        }
        out[((size_t)(b * A_ + qq)) * N4 + x] = o;
    }
}

extern "C" void kernel_launch(void* const* d_in, const int* in_sizes, int n_in,
                              void* d_out, int out_size) {
    const float* qu   = (const float*)d_in[0];   // [8,6,32]
    const float* kmat = (const float*)d_in[1];   // [8,6,1024]
    const float* v    = (const float*)d_in[2];   // [8,6,256,64,64]
    const float* Wm   = (const float*)d_in[3];   // [1024,32]
    const float* bias = (const float*)d_in[4];   // [1024]

    float* out = (float*)d_out;
    const int write_tail = ((size_t)out_size >= OUT_MAIN + (size_t)B_ * 36) ? 1 : 0;
    float* out_tail = out + OUT_MAIN;

    attn_small_kernel<<<B_, 256>>>(qu, kmat, Wm, bias, out_tail, write_tail);

    dim3 grid(N4 / 256, B_);
    combine_kernel<<<grid, 256>>>((const float4*)v, (float4*)out);
}